// round 7
// baseline (speedup 1.0000x reference)
#include <cuda_runtime.h>
#include <cstdint>
#include <cstddef>

#define RR 8
#define NN 300000
#define DD 128
#define AA 64
#define TILE_M 128
#define THREADS 512
#define HSTR 132               // h row stride: frag banks (4g+tg) distinct; online rows conflict-free
#define WSTR 72                // w1 row stride: frag banks (8tg+g) distinct
#define H_BUF (TILE_M * HSTR)  // 16896 floats
#define W_BUF (DD * WSTR)      // 9216 floats
#define LOG2E 1.4426950408889634f

__device__ __forceinline__ float fast_sigmoid(float x) {
    float e; asm("ex2.approx.f32 %0, %1;" : "=f"(e) : "f"(-LOG2E * x));
    float r; asm("rcp.approx.f32 %0, %1;" : "=f"(r) : "f"(1.0f + e));
    return r;
}
__device__ __forceinline__ float fast_exp(float x) {
    float e; asm("ex2.approx.f32 %0, %1;" : "=f"(e) : "f"(LOG2E * x));
    return e;
}

__device__ __forceinline__ void mma_tf32_16n8k8(float c[4],
                                                const unsigned a[4],
                                                unsigned b0, unsigned b1) {
    asm volatile(
        "mma.sync.aligned.m16n8k8.row.col.f32.tf32.tf32.f32 "
        "{%0,%1,%2,%3}, {%4,%5,%6,%7}, {%8,%9}, {%0,%1,%2,%3};"
        : "+f"(c[0]), "+f"(c[1]), "+f"(c[2]), "+f"(c[3])
        : "r"(a[0]), "r"(a[1]), "r"(a[2]), "r"(a[3]), "r"(b0), "r"(b1));
}

__device__ __forceinline__ void cp_async16(float* dst, const float* src, bool pred) {
    unsigned d = (unsigned)__cvta_generic_to_shared(dst);
    int sz = pred ? 16 : 0;
    asm volatile("cp.async.cg.shared.global [%0], [%1], 16, %2;"
                 :: "r"(d), "l"(src), "r"(sz));
}
#define CP_COMMIT() asm volatile("cp.async.commit_group;")
#define CP_WAIT(n)  asm volatile("cp.async.wait_group %0;" :: "n"(n))

__global__ void __launch_bounds__(THREADS, 1)
fused_m128_kernel(const float* __restrict__ h,
                  const float* __restrict__ w1,
                  const float* __restrict__ w2,
                  float* __restrict__ out) {
    extern __shared__ float smem[];
    float* sh_h   = smem;                     // 2 * H_BUF
    float* sh_w   = sh_h + 2 * H_BUF;         // 2 * W_BUF
    float* sh_w2  = sh_w + 2 * W_BUF;         // 512
    float* sh_prt = sh_w2 + RR * AA;          // 2 planes x 128

    const int tid = threadIdx.x;
    const long node0 = (long)blockIdx.x * TILE_M;

    sh_w2[tid] = w2[tid];   // 512 floats

    // stage relation rr (h tile 128x128 + W1 128x64) into buffer rr&1
    auto stage = [&](int rr) {
        const float* hg = h + (size_t)rr * NN * DD;
        float* hb = sh_h + (rr & 1) * H_BUF;
        #pragma unroll
        for (int i = 0; i < 8; i++) {
            int idx = tid + i * THREADS;       // 0..4095
            int row = idx >> 5, c4 = idx & 31;
            long node = node0 + row;
            bool p = node < NN;
            cp_async16(hb + row * HSTR + c4 * 4,
                       hg + (size_t)(p ? node : 0) * DD + c4 * 4, p);
        }
        const float* wg = w1 + (size_t)rr * DD * AA;   // row=k (128), col=n (64)
        float* wb = sh_w + (rr & 1) * W_BUF;
        #pragma unroll
        for (int i = 0; i < 4; i++) {
            int idx = tid + i * THREADS;       // 0..2047
            int row = idx >> 4, c4 = idx & 15;
            cp_async16(wb + row * WSTR + c4 * 4, wg + row * AA + c4 * 4, true);
        }
        CP_COMMIT();
    };

    stage(0);

    const int w = tid >> 5, lane = tid & 31;
    const int g = lane >> 2, tg = lane & 3;
    const int m0 = (w & 3) * 32;      // MMA warps 0-7: 4-way m split (32 rows)
    const int nh = w >> 2;            //                2-way n split (32 cols)

    // online state: thread owns row (tid&127), column quarter (tid>>7)
    const int orow = tid & 127;
    const int oq = tid >> 7;
    float4 o4[8];
    #pragma unroll
    for (int j = 0; j < 8; j++) o4[j] = make_float4(0.f, 0.f, 0.f, 0.f);
    float mrun = -1e30f, srun = 0.f;

    for (int r = 0; r < RR; r++) {
        // prefetch next relation into the other buffer (its last readers
        // finished before the S3 barrier that ended iteration r-1)
        if (r + 1 < RR) { stage(r + 1); CP_WAIT(1); }
        else            { CP_WAIT(0); }
        __syncthreads();   // S1: buf[r&1] fully staged & visible

        if (w < 8) {
            const unsigned* hh = (const unsigned*)(sh_h + (r & 1) * H_BUF);
            const unsigned* ww = (const unsigned*)(sh_w + (r & 1) * W_BUF);

            float acc[2][4][4];
            #pragma unroll
            for (int mt = 0; mt < 2; mt++)
                #pragma unroll
                for (int nt = 0; nt < 4; nt++)
                    #pragma unroll
                    for (int q = 0; q < 4; q++) acc[mt][nt][q] = 0.f;

            #pragma unroll
            for (int s = 0; s < 16; s++) {     // 16 k-steps of 8
                const int k = s * 8;
                unsigned a[2][4];
                #pragma unroll
                for (int mt = 0; mt < 2; mt++) {
                    int row = m0 + mt * 16 + g;
                    int col = k + tg;
                    a[mt][0] = hh[row * HSTR + col];
                    a[mt][1] = hh[(row + 8) * HSTR + col];
                    a[mt][2] = hh[row * HSTR + col + 4];
                    a[mt][3] = hh[(row + 8) * HSTR + col + 4];
                }
                #pragma unroll
                for (int nt = 0; nt < 4; nt++) {
                    int nb = nh * 32 + nt * 8;
                    unsigned b0 = ww[(k + tg) * WSTR + nb + g];
                    unsigned b1 = ww[(k + tg + 4) * WSTR + nb + g];
                    mma_tf32_16n8k8(acc[0][nt], a[0], b0, b1);
                    mma_tf32_16n8k8(acc[1][nt], a[1], b0, b1);
                }
            }

            // epilogue: sigmoid, dot with w2 over this warp's 32 cols
            float plo[2] = {0.f, 0.f}, phi[2] = {0.f, 0.f};
            #pragma unroll
            for (int mt = 0; mt < 2; mt++)
                #pragma unroll
                for (int nt = 0; nt < 4; nt++) {
                    int cb = nh * 32 + nt * 8 + 2 * tg;
                    float wa = sh_w2[r * AA + cb], wb2 = sh_w2[r * AA + cb + 1];
                    plo[mt] += fast_sigmoid(acc[mt][nt][0]) * wa
                             + fast_sigmoid(acc[mt][nt][1]) * wb2;
                    phi[mt] += fast_sigmoid(acc[mt][nt][2]) * wa
                             + fast_sigmoid(acc[mt][nt][3]) * wb2;
                }
            #pragma unroll
            for (int o = 1; o < 4; o <<= 1) {
                plo[0] += __shfl_xor_sync(0xffffffffu, plo[0], o);
                plo[1] += __shfl_xor_sync(0xffffffffu, plo[1], o);
                phi[0] += __shfl_xor_sync(0xffffffffu, phi[0], o);
                phi[1] += __shfl_xor_sync(0xffffffffu, phi[1], o);
            }
            if (tg == 0) {
                #pragma unroll
                for (int mt = 0; mt < 2; mt++) {
                    sh_prt[nh * TILE_M + m0 + mt * 16 + g]     = plo[mt];
                    sh_prt[nh * TILE_M + m0 + mt * 16 + g + 8] = phi[mt];
                }
            }
        }
        __syncthreads();   // S2: both score planes complete

        // online softmax update; h tile still in smem
        {
            float s = sh_prt[orow] + sh_prt[TILE_M + orow];
            float mn = fmaxf(mrun, s);
            float f = fast_exp(mrun - mn);
            float e = fast_exp(s - mn);
            srun = srun * f + e;
            mrun = mn;
            const float4* hr =
                (const float4*)(sh_h + (r & 1) * H_BUF + orow * HSTR) + oq * 8;
            #pragma unroll
            for (int j = 0; j < 8; j++) {
                float4 v = hr[j];
                o4[j].x = o4[j].x * f + e * v.x;
                o4[j].y = o4[j].y * f + e * v.y;
                o4[j].z = o4[j].z * f + e * v.z;
                o4[j].w = o4[j].w * f + e * v.w;
            }
        }
        __syncthreads();   // S3: buf[r&1] reads done before restage at r+2
    }

    // normalize + store (thread: one 128B sector of one row; lines filled by j-loop)
    float inv = 1.f / srun;
    long node = node0 + orow;
    if (node < NN) {
        float4* op = (float4*)(out + (size_t)node * DD + oq * 32);
        #pragma unroll
        for (int j = 0; j < 8; j++) {
            float4 t = o4[j];
            t.x *= inv; t.y *= inv; t.z *= inv; t.w *= inv;
            op[j] = t;
        }
    }
}

extern "C" void kernel_launch(void* const* d_in, const int* in_sizes, int n_in,
                              void* d_out, int out_size) {
    const float* h  = (const float*)d_in[0];
    const float* w1 = (const float*)d_in[1];
    const float* w2 = (const float*)d_in[2];
    float* out = (float*)d_out;

    const int smem_bytes =
        (2 * H_BUF + 2 * W_BUF + RR * AA + 2 * TILE_M) * 4;   // ~212 KB
    cudaFuncSetAttribute(fused_m128_kernel,
                         cudaFuncAttributeMaxDynamicSharedMemorySize, smem_bytes);

    dim3 grid((NN + TILE_M - 1) / TILE_M);
    fused_m128_kernel<<<grid, THREADS, smem_bytes>>>(h, w1, w2, out);
}

// round 8
// speedup vs baseline: 1.2407x; 1.2407x over previous
#include <cuda_runtime.h>
#include <cstdint>
#include <cstddef>

#define RR 8
#define NN 300000
#define DD 128
#define AA 64
#define TILE_M 128
#define HCH 36                 // h chunk row stride (32+4): frag banks 4g+tg distinct
#define WCH 72                 // w1 chunk row stride (64+8): frag banks 8tg+g distinct
#define H_SLOT (TILE_M * HCH)  // 4608 floats
#define W_SLOT (32 * WCH)      // 2304 floats
#define NCH 32                 // 8 relations x 4 k-chunks
#define LOG2E 1.4426950408889634f

__device__ __forceinline__ float fast_sigmoid(float x) {
    float e; asm("ex2.approx.f32 %0, %1;" : "=f"(e) : "f"(-LOG2E * x));
    float r; asm("rcp.approx.f32 %0, %1;" : "=f"(r) : "f"(1.0f + e));
    return r;
}

__device__ __forceinline__ void mma_tf32_16n8k8(float c[4],
                                                const unsigned a[4],
                                                unsigned b0, unsigned b1) {
    asm volatile(
        "mma.sync.aligned.m16n8k8.row.col.f32.tf32.tf32.f32 "
        "{%0,%1,%2,%3}, {%4,%5,%6,%7}, {%8,%9}, {%0,%1,%2,%3};"
        : "+f"(c[0]), "+f"(c[1]), "+f"(c[2]), "+f"(c[3])
        : "r"(a[0]), "r"(a[1]), "r"(a[2]), "r"(a[3]), "r"(b0), "r"(b1));
}

__device__ __forceinline__ void cp_async16(float* dst, const float* src, bool pred) {
    unsigned d = (unsigned)__cvta_generic_to_shared(dst);
    int sz = pred ? 16 : 0;
    asm volatile("cp.async.cg.shared.global [%0], [%1], 16, %2;"
                 :: "r"(d), "l"(src), "r"(sz));
}
#define CP_COMMIT() asm volatile("cp.async.commit_group;")
#define CP_WAIT(n)  asm volatile("cp.async.wait_group %0;" :: "n"(n))

__device__ __forceinline__ float4 ldcs4(const float4* p) {
    float4 v;
    asm volatile("ld.global.cs.v4.f32 {%0,%1,%2,%3}, [%4];"
                 : "=f"(v.x), "=f"(v.y), "=f"(v.z), "=f"(v.w) : "l"(p));
    return v;
}
__device__ __forceinline__ void stcs4(float4* p, float4 v) {
    asm volatile("st.global.cs.v4.f32 [%0], {%1,%2,%3,%4};"
                 :: "l"(p), "f"(v.x), "f"(v.y), "f"(v.z), "f"(v.w));
}

__global__ void __launch_bounds__(256, 2)
fused_kernel(const float* __restrict__ h,
             const float* __restrict__ w1,
             const float* __restrict__ w2,
             float* __restrict__ out) {
    extern __shared__ float smem[];
    float* sh_h   = smem;                       // 3 * H_SLOT
    float* sh_w   = sh_h + 3 * H_SLOT;          // 3 * W_SLOT
    float* sh_w2  = sh_w + 3 * W_SLOT;          // 512
    float* sh_sc  = sh_w2 + RR * AA;            // 8 * 128
    float* sh_prt = sh_sc + RR * TILE_M;        // 2 * 128

    const int tid = threadIdx.x;
    const long node0 = (long)blockIdx.x * TILE_M;

    // stage all w2 once
    sh_w2[tid] = w2[tid];
    sh_w2[tid + 256] = w2[tid + 256];

    // stage chunk c (relation c>>2, k-chunk c&3) into ring slot c%3
    auto stage = [&](int c) {
        int r = c >> 2, kc = c & 3;
        const float* hg = h + (size_t)r * NN * DD + kc * 32;
        float* hb = sh_h + (c % 3) * H_SLOT;
        #pragma unroll
        for (int i = 0; i < 4; i++) {
            int idx = tid + i * 256;             // 0..1023
            int row = idx >> 3, c4 = idx & 7;
            long node = node0 + row;
            bool p = node < NN;
            cp_async16(hb + row * HCH + c4 * 4,
                       hg + (size_t)(p ? node : 0) * DD + c4 * 4, p);
        }
        const float* wg = w1 + (size_t)r * DD * AA + kc * 32 * AA;
        float* wb = sh_w + (c % 3) * W_SLOT;
        #pragma unroll
        for (int i = 0; i < 2; i++) {
            int idx = tid + i * 256;             // 0..511
            int row = idx >> 4, c4 = idx & 15;
            cp_async16(wb + row * WCH + c4 * 4, wg + row * AA + c4 * 4, true);
        }
        CP_COMMIT();
    };

    stage(0);
    stage(1);

    const int w = tid >> 5, lane = tid & 31;
    const int g = lane >> 2, tg = lane & 3;
    const int m0 = (w & 3) * 32;   // 4-way m split
    const int nh = w >> 2;         // 2-way n split

    float acc[2][4][4];

    for (int c = 0; c < NCH; c++) {
        const int kc = c & 3;
        // chunk c landed (only chunk c+1's group may remain outstanding)
        if (c < NCH - 1) CP_WAIT(1); else CP_WAIT(0);
        __syncthreads();   // publish chunk c; all reads of chunk c-1 done; prt(c-1) complete

        // lag-1 score write for the relation that finished at chunk c-1
        if (c > 0 && ((c - 1) & 3) == 3 && tid < TILE_M)
            sh_sc[((c - 1) >> 2) * TILE_M + tid] = sh_prt[tid] + sh_prt[TILE_M + tid];

        // prefetch 2 ahead into slot (c+2)%3 == (c-1)%3 (readers finished above)
        if (c + 2 < NCH) stage(c + 2);

        if (kc == 0) {
            #pragma unroll
            for (int mt = 0; mt < 2; mt++)
                #pragma unroll
                for (int nt = 0; nt < 4; nt++)
                    #pragma unroll
                    for (int q = 0; q < 4; q++) acc[mt][nt][q] = 0.f;
        }

        const unsigned* hh = (const unsigned*)(sh_h + (c % 3) * H_SLOT);
        const unsigned* ww = (const unsigned*)(sh_w + (c % 3) * W_SLOT);

        #pragma unroll
        for (int kt = 0; kt < 4; kt++) {
            unsigned a[2][4];
            #pragma unroll
            for (int mt = 0; mt < 2; mt++) {
                int row = m0 + mt * 16 + g;
                int col = kt * 8 + tg;
                a[mt][0] = hh[row * HCH + col];
                a[mt][1] = hh[(row + 8) * HCH + col];
                a[mt][2] = hh[row * HCH + col + 4];
                a[mt][3] = hh[(row + 8) * HCH + col + 4];
            }
            #pragma unroll
            for (int nt = 0; nt < 4; nt++) {
                int nb = nh * 32 + nt * 8;
                unsigned b0 = ww[(kt * 8 + tg) * WCH + nb + g];
                unsigned b1 = ww[(kt * 8 + tg + 4) * WCH + nb + g];
                mma_tf32_16n8k8(acc[0][nt], a[0], b0, b1);
                mma_tf32_16n8k8(acc[1][nt], a[1], b0, b1);
            }
        }

        if (kc == 3) {
            const int r = c >> 2;
            float slo[2] = {0.f, 0.f}, shi[2] = {0.f, 0.f};
            #pragma unroll
            for (int mt = 0; mt < 2; mt++)
                #pragma unroll
                for (int nt = 0; nt < 4; nt++) {
                    int cb = nh * 32 + nt * 8 + 2 * tg;
                    float wa = sh_w2[r * AA + cb], wb2 = sh_w2[r * AA + cb + 1];
                    slo[mt] += fast_sigmoid(acc[mt][nt][0]) * wa + fast_sigmoid(acc[mt][nt][1]) * wb2;
                    shi[mt] += fast_sigmoid(acc[mt][nt][2]) * wa + fast_sigmoid(acc[mt][nt][3]) * wb2;
                }
            #pragma unroll
            for (int o = 1; o < 4; o <<= 1) {
                slo[0] += __shfl_xor_sync(0xffffffffu, slo[0], o);
                slo[1] += __shfl_xor_sync(0xffffffffu, slo[1], o);
                shi[0] += __shfl_xor_sync(0xffffffffu, shi[0], o);
                shi[1] += __shfl_xor_sync(0xffffffffu, shi[1], o);
            }
            if (tg == 0) {
                #pragma unroll
                for (int mt = 0; mt < 2; mt++) {
                    sh_prt[nh * TILE_M + m0 + mt * 16 + g]     = slo[mt];
                    sh_prt[nh * TILE_M + m0 + mt * 16 + g + 8] = shi[mt];
                }
            }
        }
    }
    __syncthreads();   // prt for r=7 complete; ring slots final

    // final score (r=7) + softmax over relations, same thread owns its row
    if (tid < TILE_M) {
        float s[RR];
        s[7] = sh_prt[tid] + sh_prt[TILE_M + tid];
        float m = s[7];
        #pragma unroll
        for (int r = 0; r < 7; r++) { s[r] = sh_sc[r * TILE_M + tid]; m = fmaxf(m, s[r]); }
        float sum = 0.f;
        #pragma unroll
        for (int r = 0; r < RR; r++) { s[r] = __expf(s[r] - m); sum += s[r]; }
        float inv = 1.f / sum;
        #pragma unroll
        for (int r = 0; r < RR; r++) sh_sc[r * TILE_M + tid] = s[r] * inv;
    }
    __syncthreads();

    // phase 3: weighted sum, REVERSED relation order (r=7 mostly from smem ring,
    // r=6..0 from L2/DRAM via .cs). Ring slots: chunk29->2, chunk30->0, chunk31->1.
    const float4* hp = (const float4*)h;
    float4* op = (float4*)out;
    #pragma unroll
    for (int i = 0; i < 16; i++) {
        int idx = tid + i * 256;
        int nrow = idx >> 5, c4 = idx & 31;
        long node = node0 + nrow;
        if (node >= NN) continue;

        float a[RR];
        #pragma unroll
        for (int r = 0; r < RR; r++) a[r] = sh_sc[r * TILE_M + nrow];

        // r = 7
        float4 acc4;
        {
            float4 v;
            int kcg = c4 >> 3;
            if (kcg == 0) {
                v = ldcs4(&hp[((size_t)7 * NN + node) * 32 + c4]);
            } else {
                const int slot_of[4] = {0, 2, 0, 1};   // kcg 1,2,3 -> slots 2,0,1
                const float* sp = sh_h + slot_of[kcg] * H_SLOT + nrow * HCH + (c4 & 7) * 4;
                v = *(const float4*)sp;
            }
            acc4.x = a[7] * v.x; acc4.y = a[7] * v.y;
            acc4.z = a[7] * v.z; acc4.w = a[7] * v.w;
        }
        // r = 6 .. 0 (most recently staged first -> L2-hot)
        #pragma unroll
        for (int r = 6; r >= 0; r--) {
            float4 v = ldcs4(&hp[((size_t)r * NN + node) * 32 + c4]);
            acc4.x += a[r] * v.x; acc4.y += a[r] * v.y;
            acc4.z += a[r] * v.z; acc4.w += a[r] * v.w;
        }
        stcs4(&op[(size_t)node * 32 + c4], acc4);
    }
}

extern "C" void kernel_launch(void* const* d_in, const int* in_sizes, int n_in,
                              void* d_out, int out_size) {
    const float* h  = (const float*)d_in[0];
    const float* w1 = (const float*)d_in[1];
    const float* w2 = (const float*)d_in[2];
    float* out = (float*)d_out;

    const int smem_bytes =
        (3 * H_SLOT + 3 * W_SLOT + RR * AA + RR * TILE_M + 2 * TILE_M) * 4;  // ~90 KB
    cudaFuncSetAttribute(fused_kernel,
                         cudaFuncAttributeMaxDynamicSharedMemorySize, smem_bytes);

    dim3 grid((NN + TILE_M - 1) / TILE_M);
    fused_kernel<<<grid, 256, smem_bytes>>>(h, w1, w2, out);
}

// round 9
// speedup vs baseline: 1.2842x; 1.0351x over previous
#include <cuda_runtime.h>
#include <cstdint>
#include <cstddef>

#define RR 8
#define NN 300000
#define DD 128
#define AA 64
#define TILE_M 128
#define HCH 68                 // h superchunk row stride (64+4): frag banks 4g+tg distinct
#define WCH 72                 // w1 row stride (64+8): frag banks 8tg+g distinct
#define H_SLOT (TILE_M * HCH)  // 8704 floats
#define W_SLOT (64 * WCH)      // 4608 floats
#define NSC 16                 // 8 relations x 2 k-halves
#define LOG2E 1.4426950408889634f

__device__ __forceinline__ float fast_sigmoid(float x) {
    float e; asm("ex2.approx.f32 %0, %1;" : "=f"(e) : "f"(-LOG2E * x));
    float r; asm("rcp.approx.f32 %0, %1;" : "=f"(r) : "f"(1.0f + e));
    return r;
}

__device__ __forceinline__ void mma_tf32_16n8k8(float c[4],
                                                const unsigned a[4],
                                                unsigned b0, unsigned b1) {
    asm volatile(
        "mma.sync.aligned.m16n8k8.row.col.f32.tf32.tf32.f32 "
        "{%0,%1,%2,%3}, {%4,%5,%6,%7}, {%8,%9}, {%0,%1,%2,%3};"
        : "+f"(c[0]), "+f"(c[1]), "+f"(c[2]), "+f"(c[3])
        : "r"(a[0]), "r"(a[1]), "r"(a[2]), "r"(a[3]), "r"(b0), "r"(b1));
}

__device__ __forceinline__ void cp_async16(float* dst, const float* src, bool pred) {
    unsigned d = (unsigned)__cvta_generic_to_shared(dst);
    int sz = pred ? 16 : 0;
    asm volatile("cp.async.cg.shared.global [%0], [%1], 16, %2;"
                 :: "r"(d), "l"(src), "r"(sz));
}
#define CP_COMMIT() asm volatile("cp.async.commit_group;")
#define CP_WAIT(n)  asm volatile("cp.async.wait_group %0;" :: "n"(n))

__device__ __forceinline__ float4 ldcs4(const float4* p) {
    float4 v;
    asm volatile("ld.global.cs.v4.f32 {%0,%1,%2,%3}, [%4];"
                 : "=f"(v.x), "=f"(v.y), "=f"(v.z), "=f"(v.w) : "l"(p));
    return v;
}
__device__ __forceinline__ void stcs4(float4* p, float4 v) {
    asm volatile("st.global.cs.v4.f32 [%0], {%1,%2,%3,%4};"
                 :: "l"(p), "f"(v.x), "f"(v.y), "f"(v.z), "f"(v.w));
}

__global__ void __launch_bounds__(256, 2)
fused_kernel(const float* __restrict__ h,
             const float* __restrict__ w1,
             const float* __restrict__ w2,
             float* __restrict__ out) {
    extern __shared__ float smem[];
    float* sh_h   = smem;                       // 2 * H_SLOT
    float* sh_w   = sh_h + 2 * H_SLOT;          // 2 * W_SLOT
    float* sh_w2  = sh_w + 2 * W_SLOT;          // 512
    float* sh_sc  = sh_w2 + RR * AA;            // 8 * 128
    float* sh_prt = sh_sc + RR * TILE_M;        // 2 * 128

    const int tid = threadIdx.x;
    const long node0 = (long)blockIdx.x * TILE_M;

    sh_w2[tid] = w2[tid];
    sh_w2[tid + 256] = w2[tid + 256];

    // stage superchunk s (relation s>>1, k-half s&1) into slot s&1
    auto stage = [&](int s) {
        int r = s >> 1, kh = s & 1;
        const float* hg = h + (size_t)r * NN * DD + kh * 64;
        float* hb = sh_h + (s & 1) * H_SLOT;
        #pragma unroll
        for (int i = 0; i < 8; i++) {
            int idx = tid + i * 256;             // 0..2047
            int row = idx >> 4, c4 = idx & 15;
            long node = node0 + row;
            bool p = node < NN;
            cp_async16(hb + row * HCH + c4 * 4,
                       hg + (size_t)(p ? node : 0) * DD + c4 * 4, p);
        }
        const float* wg = w1 + (size_t)r * DD * AA + kh * 64 * AA;
        float* wb = sh_w + (s & 1) * W_SLOT;
        #pragma unroll
        for (int i = 0; i < 4; i++) {
            int idx = tid + i * 256;             // 0..1023
            int row = idx >> 4, c4 = idx & 15;
            cp_async16(wb + row * WCH + c4 * 4, wg + row * AA + c4 * 4, true);
        }
        CP_COMMIT();
    };

    stage(0);
    CP_WAIT(0);
    __syncthreads();   // slot 0 ready

    const int w = tid >> 5, lane = tid & 31;
    const int g = lane >> 2, tg = lane & 3;
    const int m0 = (w & 3) * 32;   // 4-way m split
    const int nh = w >> 2;         // 2-way n split

    float acc[2][4][4];

    for (int s = 0; s < NSC; s++) {
        const int r = s >> 1, kh = s & 1;

        // lag-1 score write: relation (s-2)/2 finished its epilogue in iter s-1
        if (s >= 2 && (s & 1) == 0 && tid < TILE_M)
            sh_sc[((s - 2) >> 1) * TILE_M + tid] = sh_prt[tid] + sh_prt[TILE_M + tid];

        // prefetch next superchunk into the other slot
        // (its prior readers finished before the barrier that ended iter s-1)
        if (s + 1 < NSC) stage(s + 1);

        if (kh == 0) {
            #pragma unroll
            for (int mt = 0; mt < 2; mt++)
                #pragma unroll
                for (int nt = 0; nt < 4; nt++)
                    #pragma unroll
                    for (int q = 0; q < 4; q++) acc[mt][nt][q] = 0.f;
        }

        const unsigned* hh = (const unsigned*)(sh_h + (s & 1) * H_SLOT);
        const unsigned* ww = (const unsigned*)(sh_w + (s & 1) * W_SLOT);

        #pragma unroll
        for (int kt = 0; kt < 8; kt++) {
            unsigned a[2][4];
            #pragma unroll
            for (int mt = 0; mt < 2; mt++) {
                int row = m0 + mt * 16 + g;
                int col = kt * 8 + tg;
                a[mt][0] = hh[row * HCH + col];
                a[mt][1] = hh[(row + 8) * HCH + col];
                a[mt][2] = hh[row * HCH + col + 4];
                a[mt][3] = hh[(row + 8) * HCH + col + 4];
            }
            #pragma unroll
            for (int nt = 0; nt < 4; nt++) {
                int nb = nh * 32 + nt * 8;
                unsigned b0 = ww[(kt * 8 + tg) * WCH + nb + g];
                unsigned b1 = ww[(kt * 8 + tg + 4) * WCH + nb + g];
                mma_tf32_16n8k8(acc[0][nt], a[0], b0, b1);
                mma_tf32_16n8k8(acc[1][nt], a[1], b0, b1);
            }
        }

        if (kh == 1) {
            // epilogue: sigmoid, dot with w2 over this warp's 32 cols
            float slo[2] = {0.f, 0.f}, shi[2] = {0.f, 0.f};
            #pragma unroll
            for (int mt = 0; mt < 2; mt++)
                #pragma unroll
                for (int nt = 0; nt < 4; nt++) {
                    int cb = nh * 32 + nt * 8 + 2 * tg;
                    float wa = sh_w2[r * AA + cb], wb2 = sh_w2[r * AA + cb + 1];
                    slo[mt] += fast_sigmoid(acc[mt][nt][0]) * wa + fast_sigmoid(acc[mt][nt][1]) * wb2;
                    shi[mt] += fast_sigmoid(acc[mt][nt][2]) * wa + fast_sigmoid(acc[mt][nt][3]) * wb2;
                }
            #pragma unroll
            for (int o = 1; o < 4; o <<= 1) {
                slo[0] += __shfl_xor_sync(0xffffffffu, slo[0], o);
                slo[1] += __shfl_xor_sync(0xffffffffu, slo[1], o);
                shi[0] += __shfl_xor_sync(0xffffffffu, shi[0], o);
                shi[1] += __shfl_xor_sync(0xffffffffu, shi[1], o);
            }
            if (tg == 0) {
                #pragma unroll
                for (int mt = 0; mt < 2; mt++) {
                    sh_prt[nh * TILE_M + m0 + mt * 16 + g]     = slo[mt];
                    sh_prt[nh * TILE_M + m0 + mt * 16 + g + 8] = shi[mt];
                }
            }
        }

        // staged data for s+1 has had a full superchunk of compute to land
        if (s + 1 < NSC) CP_WAIT(0);
        __syncthreads();   // publish slot (s+1)&1; all reads of slot s&1 done
    }

    // final score (r=7) + softmax over relations
    if (tid < TILE_M) {
        float sv[RR];
        sv[7] = sh_prt[tid] + sh_prt[TILE_M + tid];
        float m = sv[7];
        #pragma unroll
        for (int r = 0; r < 7; r++) { sv[r] = sh_sc[r * TILE_M + tid]; m = fmaxf(m, sv[r]); }
        float sum = 0.f;
        #pragma unroll
        for (int r = 0; r < RR; r++) { sv[r] = __expf(sv[r] - m); sum += sv[r]; }
        float inv = 1.f / sum;
        #pragma unroll
        for (int r = 0; r < RR; r++) sh_sc[r * TILE_M + tid] = sv[r] * inv;
    }
    __syncthreads();

    // phase 3: weighted sum. r=7 entirely from the smem ring
    // (slot 0 holds k[0:64), slot 1 holds k[64:128)); r=6..0 via .cs from L2/DRAM.
    const float4* hp = (const float4*)h;
    float4* op = (float4*)out;
    #pragma unroll
    for (int i = 0; i < 16; i++) {
        int idx = tid + i * 256;
        int nrow = idx >> 5, c4 = idx & 31;
        long node = node0 + nrow;
        if (node >= NN) continue;

        float a[RR];
        #pragma unroll
        for (int r = 0; r < RR; r++) a[r] = sh_sc[r * TILE_M + nrow];

        float4 acc4;
        {
            const float* sp = sh_h + (c4 >> 4) * H_SLOT + nrow * HCH + (c4 & 15) * 4;
            float4 v = *(const float4*)sp;
            acc4.x = a[7] * v.x; acc4.y = a[7] * v.y;
            acc4.z = a[7] * v.z; acc4.w = a[7] * v.w;
        }
        #pragma unroll
        for (int r = 6; r >= 0; r--) {
            float4 v = ldcs4(&hp[((size_t)r * NN + node) * 32 + c4]);
            acc4.x += a[r] * v.x; acc4.y += a[r] * v.y;
            acc4.z += a[r] * v.z; acc4.w += a[r] * v.w;
        }
        stcs4(&op[(size_t)node * 32 + c4], acc4);
    }
}

extern "C" void kernel_launch(void* const* d_in, const int* in_sizes, int n_in,
                              void* d_out, int out_size) {
    const float* h  = (const float*)d_in[0];
    const float* w1 = (const float*)d_in[1];
    const float* w2 = (const float*)d_in[2];
    float* out = (float*)d_out;

    const int smem_bytes =
        (2 * H_SLOT + 2 * W_SLOT + RR * AA + RR * TILE_M + 2 * TILE_M) * 4;  // ~111 KB
    cudaFuncSetAttribute(fused_kernel,
                         cudaFuncAttributeMaxDynamicSharedMemorySize, smem_bytes);

    dim3 grid((NN + TILE_M - 1) / TILE_M);
    fused_kernel<<<grid, 256, smem_bytes>>>(h, w1, w2, out);
}

// round 10
// speedup vs baseline: 1.3815x; 1.0758x over previous
#include <cuda_runtime.h>
#include <cstdint>
#include <cstddef>

#define RR 8
#define NN 300000
#define DD 128
#define AA 64
#define TILE_M 128
#define HCH 68                 // h superchunk row stride (64+4): frag banks 4g+tg distinct
#define WCH 72                 // w1 row stride (64+8): frag banks 8tg+g distinct
#define H_SLOT (TILE_M * HCH)  // 8704 floats
#define W_SLOT (64 * WCH)      // 4608 floats
#define NSC 16                 // 8 relations x 2 k-halves
#define LOG2E 1.4426950408889634f

__device__ __forceinline__ float fast_sigmoid(float x) {
    float e; asm("ex2.approx.f32 %0, %1;" : "=f"(e) : "f"(-LOG2E * x));
    float r; asm("rcp.approx.f32 %0, %1;" : "=f"(r) : "f"(1.0f + e));
    return r;
}
__device__ __forceinline__ float fast_exp(float x) {
    float e; asm("ex2.approx.f32 %0, %1;" : "=f"(e) : "f"(LOG2E * x));
    return e;
}

__device__ __forceinline__ void mma_tf32_16n8k8(float c[4],
                                                const unsigned a[4],
                                                unsigned b0, unsigned b1) {
    asm volatile(
        "mma.sync.aligned.m16n8k8.row.col.f32.tf32.tf32.f32 "
        "{%0,%1,%2,%3}, {%4,%5,%6,%7}, {%8,%9}, {%0,%1,%2,%3};"
        : "+f"(c[0]), "+f"(c[1]), "+f"(c[2]), "+f"(c[3])
        : "r"(a[0]), "r"(a[1]), "r"(a[2]), "r"(a[3]), "r"(b0), "r"(b1));
}

__device__ __forceinline__ void cp_async16(float* dst, const float* src, bool pred) {
    unsigned d = (unsigned)__cvta_generic_to_shared(dst);
    int sz = pred ? 16 : 0;
    asm volatile("cp.async.cg.shared.global [%0], [%1], 16, %2;"
                 :: "r"(d), "l"(src), "r"(sz));
}
#define CP_COMMIT() asm volatile("cp.async.commit_group;")
#define CP_WAIT(n)  asm volatile("cp.async.wait_group %0;" :: "n"(n))

__device__ __forceinline__ float4 ldcs4(const float4* p) {
    float4 v;
    asm volatile("ld.global.cs.v4.f32 {%0,%1,%2,%3}, [%4];"
                 : "=f"(v.x), "=f"(v.y), "=f"(v.z), "=f"(v.w) : "l"(p));
    return v;
}
__device__ __forceinline__ void stcs4(float4* p, float4 v) {
    asm volatile("st.global.cs.v4.f32 [%0], {%1,%2,%3,%4};"
                 :: "l"(p), "f"(v.x), "f"(v.y), "f"(v.z), "f"(v.w));
}

__global__ void __launch_bounds__(256, 2)
fused_kernel(const float* __restrict__ h,
             const float* __restrict__ w1,
             const float* __restrict__ w2,
             float* __restrict__ out) {
    extern __shared__ float smem[];
    float* sh_h   = smem;                       // 2 * H_SLOT
    float* sh_w   = sh_h + 2 * H_SLOT;          // 2 * W_SLOT
    float* sh_w2  = sh_w + 2 * W_SLOT;          // 512
    float* sh_sc  = sh_w2 + RR * AA;            // 8 * 128
    float* sh_prt = sh_sc + RR * TILE_M;        // 2 * 128

    const int tid = threadIdx.x;
    const long node0 = (long)blockIdx.x * TILE_M;

    sh_w2[tid] = w2[tid];
    sh_w2[tid + 256] = w2[tid + 256];

    // one h staging piece (256 float4) for superchunk s
    auto stage_h_piece = [&](int s, int i) {
        int r = s >> 1, kh = s & 1;
        const float* hg = h + (size_t)r * NN * DD + kh * 64;
        float* hb = sh_h + (s & 1) * H_SLOT;
        int idx = tid + i * 256;                 // 0..2047
        int row = idx >> 4, c4 = idx & 15;
        long node = node0 + row;
        bool p = node < NN;
        cp_async16(hb + row * HCH + c4 * 4,
                   hg + (size_t)(p ? node : 0) * DD + c4 * 4, p);
    };
    // one w staging piece (256 float4) for superchunk s
    auto stage_w_piece = [&](int s, int i) {
        int r = s >> 1, kh = s & 1;
        const float* wg = w1 + (size_t)r * DD * AA + kh * 64 * AA;
        float* wb = sh_w + (s & 1) * W_SLOT;
        int idx = tid + i * 256;                 // 0..1023
        int row = idx >> 4, c4 = idx & 15;
        cp_async16(wb + row * WCH + c4 * 4, wg + row * AA + c4 * 4, true);
    };

    // prologue: stage superchunk 0 fully
    #pragma unroll
    for (int i = 0; i < 8; i++) stage_h_piece(0, i);
    #pragma unroll
    for (int i = 0; i < 4; i++) stage_w_piece(0, i);
    CP_COMMIT();

    const int w = tid >> 5, lane = tid & 31;
    const int g = lane >> 2, tg = lane & 3;
    const int m0 = (w & 3) * 32;   // 4-way m split
    const int nh = w >> 2;         // 2-way n split

    float acc[2][4][4];

    for (int s = 0; s < NSC; s++) {
        const int r = s >> 1, kh = s & 1;

        CP_WAIT(0);        // group(s) (committed mid-iteration s-1) has landed
        __syncthreads();   // publish slot s&1; all reads/writes of prior epoch done

        // lag-1 score write: relation (s-2)/2 finished its epilogue in iter s-1
        if (s >= 2 && (s & 1) == 0 && tid < TILE_M)
            sh_sc[((s - 2) >> 1) * TILE_M + tid] = sh_prt[tid] + sh_prt[TILE_M + tid];

        if (kh == 0) {
            #pragma unroll
            for (int mt = 0; mt < 2; mt++)
                #pragma unroll
                for (int nt = 0; nt < 4; nt++)
                    #pragma unroll
                    for (int q = 0; q < 4; q++) acc[mt][nt][q] = 0.f;
        }

        const unsigned* hh = (const unsigned*)(sh_h + (s & 1) * H_SLOT);
        const unsigned* ww = (const unsigned*)(sh_w + (s & 1) * W_SLOT);
        const bool do_stage = (s + 1 < NSC);

        #pragma unroll
        for (int kt = 0; kt < 8; kt++) {
            // de-burst staging: 3 pieces per kt for kt=0..3 (12 pieces total)
            if (kt < 4 && do_stage) {
                stage_h_piece(s + 1, 2 * kt);
                stage_h_piece(s + 1, 2 * kt + 1);
                stage_w_piece(s + 1, kt);
                if (kt == 3) CP_COMMIT();
            }
            unsigned a[2][4];
            #pragma unroll
            for (int mt = 0; mt < 2; mt++) {
                int row = m0 + mt * 16 + g;
                int col = kt * 8 + tg;
                a[mt][0] = hh[row * HCH + col];
                a[mt][1] = hh[(row + 8) * HCH + col];
                a[mt][2] = hh[row * HCH + col + 4];
                a[mt][3] = hh[(row + 8) * HCH + col + 4];
            }
            #pragma unroll
            for (int nt = 0; nt < 4; nt++) {
                int nb = nh * 32 + nt * 8;
                unsigned b0 = ww[(kt * 8 + tg) * WCH + nb + g];
                unsigned b1 = ww[(kt * 8 + tg + 4) * WCH + nb + g];
                mma_tf32_16n8k8(acc[0][nt], a[0], b0, b1);
                mma_tf32_16n8k8(acc[1][nt], a[1], b0, b1);
            }
        }

        if (kh == 1) {
            // epilogue: sigmoid, dot with w2 over this warp's 32 cols
            float slo[2] = {0.f, 0.f}, shi[2] = {0.f, 0.f};
            #pragma unroll
            for (int mt = 0; mt < 2; mt++)
                #pragma unroll
                for (int nt = 0; nt < 4; nt++) {
                    int cb = nh * 32 + nt * 8 + 2 * tg;
                    float wa = sh_w2[r * AA + cb], wb2 = sh_w2[r * AA + cb + 1];
                    slo[mt] += fast_sigmoid(acc[mt][nt][0]) * wa + fast_sigmoid(acc[mt][nt][1]) * wb2;
                    shi[mt] += fast_sigmoid(acc[mt][nt][2]) * wa + fast_sigmoid(acc[mt][nt][3]) * wb2;
                }
            #pragma unroll
            for (int o = 1; o < 4; o <<= 1) {
                slo[0] += __shfl_xor_sync(0xffffffffu, slo[0], o);
                slo[1] += __shfl_xor_sync(0xffffffffu, slo[1], o);
                shi[0] += __shfl_xor_sync(0xffffffffu, shi[0], o);
                shi[1] += __shfl_xor_sync(0xffffffffu, shi[1], o);
            }
            if (tg == 0) {
                #pragma unroll
                for (int mt = 0; mt < 2; mt++) {
                    sh_prt[nh * TILE_M + m0 + mt * 16 + g]     = slo[mt];
                    sh_prt[nh * TILE_M + m0 + mt * 16 + g + 8] = shi[mt];
                }
            }
        }
    }
    __syncthreads();   // prt for r=7 complete; ring slots final

    // final score (r=7) + softmax over relations
    if (tid < TILE_M) {
        float sv[RR];
        sv[7] = sh_prt[tid] + sh_prt[TILE_M + tid];
        float m = sv[7];
        #pragma unroll
        for (int r = 0; r < 7; r++) { sv[r] = sh_sc[r * TILE_M + tid]; m = fmaxf(m, sv[r]); }
        float sum = 0.f;
        #pragma unroll
        for (int r = 0; r < RR; r++) { sv[r] = fast_exp(sv[r] - m); sum += sv[r]; }
        float inv = 1.f / sum;
        #pragma unroll
        for (int r = 0; r < RR; r++) sh_sc[r * TILE_M + tid] = sv[r] * inv;
    }
    __syncthreads();

    // phase 3: weighted sum. r=7 entirely from the smem ring
    // (slot 0 holds k[0:64), slot 1 holds k[64:128)); r=6..0 via .cs from L2/DRAM.
    const float4* hp = (const float4*)h;
    float4* op = (float4*)out;
    #pragma unroll 4
    for (int i = 0; i < 16; i++) {
        int idx = tid + i * 256;
        int nrow = idx >> 5, c4 = idx & 31;
        long node = node0 + nrow;
        if (node >= NN) continue;

        float a[RR];
        #pragma unroll
        for (int r = 0; r < RR; r++) a[r] = sh_sc[r * TILE_M + nrow];

        float4 acc4;
        {
            const float* sp = sh_h + (c4 >> 4) * H_SLOT + nrow * HCH + (c4 & 15) * 4;
            float4 v = *(const float4*)sp;
            acc4.x = a[7] * v.x; acc4.y = a[7] * v.y;
            acc4.z = a[7] * v.z; acc4.w = a[7] * v.w;
        }
        #pragma unroll
        for (int r = 6; r >= 0; r--) {
            float4 v = ldcs4(&hp[((size_t)r * NN + node) * 32 + c4]);
            acc4.x += a[r] * v.x; acc4.y += a[r] * v.y;
            acc4.z += a[r] * v.z; acc4.w += a[r] * v.w;
        }
        stcs4(&op[(size_t)node * 32 + c4], acc4);
    }
}

extern "C" void kernel_launch(void* const* d_in, const int* in_sizes, int n_in,
                              void* d_out, int out_size) {
    const float* h  = (const float*)d_in[0];
    const float* w1 = (const float*)d_in[1];
    const float* w2 = (const float*)d_in[2];
    float* out = (float*)d_out;

    const int smem_bytes =
        (2 * H_SLOT + 2 * W_SLOT + RR * AA + RR * TILE_M + 2 * TILE_M) * 4;  // ~111 KB
    cudaFuncSetAttribute(fused_kernel,
                         cudaFuncAttributeMaxDynamicSharedMemorySize, smem_bytes);

    dim3 grid((NN + TILE_M - 1) / TILE_M);
    fused_kernel<<<grid, 256, smem_bytes>>>(h, w1, w2, out);
}

// round 11
// speedup vs baseline: 1.3983x; 1.0121x over previous
#include <cuda_runtime.h>
#include <cstdint>
#include <cstddef>

#define RR 8
#define NN 300000
#define DD 128
#define AA 64
#define TILE_M 128
#define HCH 36                 // h chunk row stride (32+4): frag banks 4g+tg distinct
#define WCH 72                 // w1 row stride (64+8): frag banks 8tg+g distinct
#define H_SLOT (TILE_M * HCH)  // 4608 floats
#define W_SLOT (32 * WCH)      // 2304 floats
#define NCH 32                 // 8 relations x 4 k-chunks
#define LOG2E 1.4426950408889634f

__device__ __forceinline__ float fast_sigmoid(float x) {
    float e; asm("ex2.approx.f32 %0, %1;" : "=f"(e) : "f"(-LOG2E * x));
    float r; asm("rcp.approx.f32 %0, %1;" : "=f"(r) : "f"(1.0f + e));
    return r;
}
__device__ __forceinline__ float fast_exp(float x) {
    float e; asm("ex2.approx.f32 %0, %1;" : "=f"(e) : "f"(LOG2E * x));
    return e;
}

__device__ __forceinline__ void mma_tf32_16n8k8(float c[4],
                                                const unsigned a[4],
                                                unsigned b0, unsigned b1) {
    asm volatile(
        "mma.sync.aligned.m16n8k8.row.col.f32.tf32.tf32.f32 "
        "{%0,%1,%2,%3}, {%4,%5,%6,%7}, {%8,%9}, {%0,%1,%2,%3};"
        : "+f"(c[0]), "+f"(c[1]), "+f"(c[2]), "+f"(c[3])
        : "r"(a[0]), "r"(a[1]), "r"(a[2]), "r"(a[3]), "r"(b0), "r"(b1));
}

__device__ __forceinline__ void cp_async16(float* dst, const float* src, bool pred) {
    unsigned d = (unsigned)__cvta_generic_to_shared(dst);
    int sz = pred ? 16 : 0;
    asm volatile("cp.async.cg.shared.global [%0], [%1], 16, %2;"
                 :: "r"(d), "l"(src), "r"(sz));
}
#define CP_COMMIT() asm volatile("cp.async.commit_group;")
#define CP_WAIT(n)  asm volatile("cp.async.wait_group %0;" :: "n"(n))

__device__ __forceinline__ float4 ldcs4(const float4* p) {
    float4 v;
    asm volatile("ld.global.cs.v4.f32 {%0,%1,%2,%3}, [%4];"
                 : "=f"(v.x), "=f"(v.y), "=f"(v.z), "=f"(v.w) : "l"(p));
    return v;
}
__device__ __forceinline__ void stcs4(float4* p, float4 v) {
    asm volatile("st.global.cs.v4.f32 [%0], {%1,%2,%3,%4};"
                 :: "l"(p), "f"(v.x), "f"(v.y), "f"(v.z), "f"(v.w));
}

__global__ void __launch_bounds__(256, 3)
fused_kernel(const float* __restrict__ h,
             const float* __restrict__ w1,
             const float* __restrict__ w2,
             float* __restrict__ out) {
    extern __shared__ float smem[];
    float* sh_h   = smem;                       // 2 * H_SLOT
    float* sh_w   = sh_h + 2 * H_SLOT;          // 2 * W_SLOT
    float* sh_w2  = sh_w + 2 * W_SLOT;          // 512
    float* sh_sc  = sh_w2 + RR * AA;            // 8 * 128
    float* sh_prt = sh_sc + RR * TILE_M;        // 2 * 128

    const int tid = threadIdx.x;
    const long node0 = (long)blockIdx.x * TILE_M;

    sh_w2[tid] = w2[tid];
    sh_w2[tid + 256] = w2[tid + 256];

    // one h staging piece (256 float4) of chunk c (relation c>>2, k-chunk c&3)
    auto stage_h_piece = [&](int c, int i) {
        int r = c >> 2, kc = c & 3;
        const float* hg = h + (size_t)r * NN * DD + kc * 32;
        float* hb = sh_h + (c & 1) * H_SLOT;
        int idx = tid + i * 256;                 // 0..1023
        int row = idx >> 3, c4 = idx & 7;
        long node = node0 + row;
        bool p = node < NN;
        cp_async16(hb + row * HCH + c4 * 4,
                   hg + (size_t)(p ? node : 0) * DD + c4 * 4, p);
    };
    // one w staging piece (256 float4) of chunk c
    auto stage_w_piece = [&](int c, int i) {
        int r = c >> 2, kc = c & 3;
        const float* wg = w1 + (size_t)r * DD * AA + kc * 32 * AA;
        float* wb = sh_w + (c & 1) * W_SLOT;
        int idx = tid + i * 256;                 // 0..511
        int row = idx >> 4, c4 = idx & 15;
        cp_async16(wb + row * WCH + c4 * 4, wg + row * AA + c4 * 4, true);
    };

    // prologue: stage chunk 0 fully
    #pragma unroll
    for (int i = 0; i < 4; i++) stage_h_piece(0, i);
    #pragma unroll
    for (int i = 0; i < 2; i++) stage_w_piece(0, i);
    CP_COMMIT();

    const int w = tid >> 5, lane = tid & 31;
    const int g = lane >> 2, tg = lane & 3;
    const int m0 = (w & 3) * 32;   // 4-way m split
    const int nh = w >> 2;         // 2-way n split

    float acc[2][4][4];

    for (int c = 0; c < NCH; c++) {
        const int kc = c & 3;

        CP_WAIT(0);        // group for chunk c (committed during iter c-1) landed
        __syncthreads();   // publish slot c&1; all prior reads/writes ordered

        // lag-1 score write: relation (c-1)/4 finished its epilogue in iter c-1
        if (c >= 1 && (c & 3) == 0 && tid < TILE_M)
            sh_sc[((c - 1) >> 2) * TILE_M + tid] = sh_prt[tid] + sh_prt[TILE_M + tid];

        if (kc == 0) {
            #pragma unroll
            for (int mt = 0; mt < 2; mt++)
                #pragma unroll
                for (int nt = 0; nt < 4; nt++)
                    #pragma unroll
                    for (int q = 0; q < 4; q++) acc[mt][nt][q] = 0.f;
        }

        const unsigned* hh = (const unsigned*)(sh_h + (c & 1) * H_SLOT);
        const unsigned* ww = (const unsigned*)(sh_w + (c & 1) * W_SLOT);
        const bool do_stage = (c + 1 < NCH);

        #pragma unroll
        for (int kt = 0; kt < 4; kt++) {
            // de-burst staging of chunk c+1 into slot (c+1)&1
            if (do_stage) {
                if (kt < 2) {
                    stage_h_piece(c + 1, 2 * kt);
                    stage_h_piece(c + 1, 2 * kt + 1);
                } else if (kt == 2) {
                    stage_w_piece(c + 1, 0);
                    stage_w_piece(c + 1, 1);
                    CP_COMMIT();
                }
            }
            unsigned a[2][4];
            #pragma unroll
            for (int mt = 0; mt < 2; mt++) {
                int row = m0 + mt * 16 + g;
                int col = kt * 8 + tg;
                a[mt][0] = hh[row * HCH + col];
                a[mt][1] = hh[(row + 8) * HCH + col];
                a[mt][2] = hh[row * HCH + col + 4];
                a[mt][3] = hh[(row + 8) * HCH + col + 4];
            }
            #pragma unroll
            for (int nt = 0; nt < 4; nt++) {
                int nb = nh * 32 + nt * 8;
                unsigned b0 = ww[(kt * 8 + tg) * WCH + nb + g];
                unsigned b1 = ww[(kt * 8 + tg + 4) * WCH + nb + g];
                mma_tf32_16n8k8(acc[0][nt], a[0], b0, b1);
                mma_tf32_16n8k8(acc[1][nt], a[1], b0, b1);
            }
        }

        if (kc == 3) {
            const int r = c >> 2;
            float slo[2] = {0.f, 0.f}, shi[2] = {0.f, 0.f};
            #pragma unroll
            for (int mt = 0; mt < 2; mt++)
                #pragma unroll
                for (int nt = 0; nt < 4; nt++) {
                    int cb = nh * 32 + nt * 8 + 2 * tg;
                    float wa = sh_w2[r * AA + cb], wb2 = sh_w2[r * AA + cb + 1];
                    slo[mt] += fast_sigmoid(acc[mt][nt][0]) * wa + fast_sigmoid(acc[mt][nt][1]) * wb2;
                    shi[mt] += fast_sigmoid(acc[mt][nt][2]) * wa + fast_sigmoid(acc[mt][nt][3]) * wb2;
                }
            #pragma unroll
            for (int o = 1; o < 4; o <<= 1) {
                slo[0] += __shfl_xor_sync(0xffffffffu, slo[0], o);
                slo[1] += __shfl_xor_sync(0xffffffffu, slo[1], o);
                shi[0] += __shfl_xor_sync(0xffffffffu, shi[0], o);
                shi[1] += __shfl_xor_sync(0xffffffffu, shi[1], o);
            }
            if (tg == 0) {
                #pragma unroll
                for (int mt = 0; mt < 2; mt++) {
                    sh_prt[nh * TILE_M + m0 + mt * 16 + g]     = slo[mt];
                    sh_prt[nh * TILE_M + m0 + mt * 16 + g + 8] = shi[mt];
                }
            }
        }
    }
    __syncthreads();   // prt for r=7 complete; ring slots final

    // final score (r=7) + softmax over relations
    if (tid < TILE_M) {
        float sv[RR];
        sv[7] = sh_prt[tid] + sh_prt[TILE_M + tid];
        float m = sv[7];
        #pragma unroll
        for (int r = 0; r < 7; r++) { sv[r] = sh_sc[r * TILE_M + tid]; m = fmaxf(m, sv[r]); }
        float sum = 0.f;
        #pragma unroll
        for (int r = 0; r < RR; r++) { sv[r] = fast_exp(sv[r] - m); sum += sv[r]; }
        float inv = 1.f / sum;
        #pragma unroll
        for (int r = 0; r < RR; r++) sh_sc[r * TILE_M + tid] = sv[r] * inv;
    }
    __syncthreads();

    // phase 3: weighted sum. r=7 cols 64..127 from the smem ring
    // (slot0 = chunk30 = k[64:96), slot1 = chunk31 = k[96:128)); rest via .cs.
    const float4* hp = (const float4*)h;
    float4* op = (float4*)out;
    #pragma unroll 4
    for (int i = 0; i < 16; i++) {
        int idx = tid + i * 256;
        int nrow = idx >> 5, c4 = idx & 31;
        long node = node0 + nrow;
        if (node >= NN) continue;

        float a[RR];
        #pragma unroll
        for (int r = 0; r < RR; r++) a[r] = sh_sc[r * TILE_M + nrow];

        float4 acc4;
        {
            float4 v;
            if (c4 < 16) {
                v = ldcs4(&hp[((size_t)7 * NN + node) * 32 + c4]);
            } else {
                const float* sp = sh_h + ((c4 >> 3) & 1) * H_SLOT
                                + nrow * HCH + (c4 & 7) * 4;
                v = *(const float4*)sp;
            }
            acc4.x = a[7] * v.x; acc4.y = a[7] * v.y;
            acc4.z = a[7] * v.z; acc4.w = a[7] * v.w;
        }
        #pragma unroll
        for (int r = 6; r >= 0; r--) {
            float4 v = ldcs4(&hp[((size_t)r * NN + node) * 32 + c4]);
            acc4.x += a[r] * v.x; acc4.y += a[r] * v.y;
            acc4.z += a[r] * v.z; acc4.w += a[r] * v.w;
        }
        stcs4(&op[(size_t)node * 32 + c4], acc4);
    }
}

extern "C" void kernel_launch(void* const* d_in, const int* in_sizes, int n_in,
                              void* d_out, int out_size) {
    const float* h  = (const float*)d_in[0];
    const float* w1 = (const float*)d_in[1];
    const float* w2 = (const float*)d_in[2];
    float* out = (float*)d_out;

    const int smem_bytes =
        (2 * H_SLOT + 2 * W_SLOT + RR * AA + RR * TILE_M + 2 * TILE_M) * 4;  // ~61 KB
    cudaFuncSetAttribute(fused_kernel,
                         cudaFuncAttributeMaxDynamicSharedMemorySize, smem_bytes);

    dim3 grid((NN + TILE_M - 1) / TILE_M);
    fused_kernel<<<grid, 256, smem_bytes>>>(h, w1, w2, out);
}

// round 12
// speedup vs baseline: 1.4962x; 1.0700x over previous
#include <cuda_runtime.h>
#include <cstdint>
#include <cstddef>

#define RR 8
#define NN 300000
#define DD 128
#define AA 64
#define TILE_M 128
#define HCH 36                 // h chunk row stride (32+4): frag banks 4g+tg distinct
#define WCH 72                 // w1 row stride (64+8): frag banks 8tg+g distinct
#define H_SLOT (TILE_M * HCH)  // 4608 floats
#define W_SLOT (32 * WCH)      // 2304 floats
#define NCH 32                 // 8 relations x 4 k-chunks
#define LOG2E 1.4426950408889634f

__device__ __forceinline__ float fast_sigmoid(float x) {
    float t;
    asm("tanh.approx.f32 %0, %1;" : "=f"(t) : "f"(0.5f * x));
    return fmaf(t, 0.5f, 0.5f);
}
__device__ __forceinline__ float fast_exp(float x) {
    float e; asm("ex2.approx.f32 %0, %1;" : "=f"(e) : "f"(LOG2E * x));
    return e;
}

__device__ __forceinline__ void mma_tf32_16n8k8(float c[4],
                                                const unsigned a[4],
                                                unsigned b0, unsigned b1) {
    asm volatile(
        "mma.sync.aligned.m16n8k8.row.col.f32.tf32.tf32.f32 "
        "{%0,%1,%2,%3}, {%4,%5,%6,%7}, {%8,%9}, {%0,%1,%2,%3};"
        : "+f"(c[0]), "+f"(c[1]), "+f"(c[2]), "+f"(c[3])
        : "r"(a[0]), "r"(a[1]), "r"(a[2]), "r"(a[3]), "r"(b0), "r"(b1));
}

__device__ __forceinline__ void cp_async16_s(uint32_t dst, const float* src) {
    asm volatile("cp.async.cg.shared.global [%0], [%1], 16;"
                 :: "r"(dst), "l"(src));
}
#define CP_COMMIT() asm volatile("cp.async.commit_group;")
#define CP_WAIT(n)  asm volatile("cp.async.wait_group %0;" :: "n"(n))

__device__ __forceinline__ float4 ldcs4(const float4* p) {
    float4 v;
    asm volatile("ld.global.cs.v4.f32 {%0,%1,%2,%3}, [%4];"
                 : "=f"(v.x), "=f"(v.y), "=f"(v.z), "=f"(v.w) : "l"(p));
    return v;
}
__device__ __forceinline__ void stcs4(float4* p, float4 v) {
    asm volatile("st.global.cs.v4.f32 [%0], {%1,%2,%3,%4};"
                 :: "l"(p), "f"(v.x), "f"(v.y), "f"(v.z), "f"(v.w));
}

__device__ __forceinline__ uint32_t smem_u32(const void* p) {
    uint32_t a;
    asm("{ .reg .u64 t; cvta.to.shared.u64 t, %1; cvt.u32.u64 %0, t; }"
        : "=r"(a) : "l"(p));
    return a;
}

__global__ void __launch_bounds__(256, 3)
fused_kernel(const float* __restrict__ h,
             const float* __restrict__ w1,
             const float* __restrict__ w2,
             float* __restrict__ out) {
    extern __shared__ float smem[];
    float* sh_h   = smem;                       // 2 * H_SLOT
    float* sh_w   = sh_h + 2 * H_SLOT;          // 2 * W_SLOT
    float* sh_w2  = sh_w + 2 * W_SLOT;          // 512
    float* sh_sc  = sh_w2 + RR * AA;            // 8 * 128
    float* sh_prt = sh_sc + RR * TILE_M;        // 2 * 128

    const int tid = threadIdx.x;
    const long node0 = (long)blockIdx.x * TILE_M;
    const bool boundary = (node0 + TILE_M > NN);   // uniform; true for 1 block

    sh_w2[tid] = w2[tid];
    sh_w2[tid + 256] = w2[tid + 256];

    // ---- per-thread staging constants (clamped addressing) ----
    // h piece i: idx = tid + i*256, row = idx>>3 (row step/piece = 32), c4 = idx&7
    const int hrow0 = tid >> 3, hc4 = tid & 7;
    const size_t hoff0 = (size_t)(node0 + hrow0) * DD + hc4 * 4;  // valid for !boundary
    const uint32_t hB = smem_u32(sh_h);
    const uint32_t hdst0 = hB + (uint32_t)(hrow0 * HCH + hc4 * 4) * 4;
    // w piece i: idx = tid + i*256, row = idx>>4 (row step/piece = 16), c4 = idx&15
    const int wrow0 = tid >> 4, wc4 = tid & 15;
    const size_t woff0 = (size_t)wrow0 * AA + wc4 * 4;
    const uint32_t wB = smem_u32(sh_w);
    const uint32_t wdst0 = wB + (uint32_t)(wrow0 * WCH + wc4 * 4) * 4;

    // per-piece global h offset (clamp only in the boundary block)
    auto h_off = [&](int i) -> size_t {
        if (!boundary) return hoff0 + (size_t)i * (32 * DD);
        long node = node0 + hrow0 + i * 32;
        if (node >= NN) node = NN - 1;
        return (size_t)node * DD + hc4 * 4;
    };

    // stage chunk c fully (prologue) or piece-wise (main loop)
    const size_t NND = (size_t)NN * DD;

    // prologue: stage chunk 0
    {
        const float* hs = h;                       // r=0, kc=0
        const float* ws = w1;
        #pragma unroll
        for (int i = 0; i < 4; i++)
            cp_async16_s(hdst0 + i * (32 * HCH * 4), hs + h_off(i));
        #pragma unroll
        for (int i = 0; i < 2; i++)
            cp_async16_s(wdst0 + i * (16 * WCH * 4), ws + woff0 + i * (16 * AA));
        CP_COMMIT();
    }

    const int w = tid >> 5, lane = tid & 31;
    const int g = lane >> 2, tg = lane & 3;
    const int m0 = (w & 3) * 32;   // 4-way m split
    const int nh = w >> 2;         // 2-way n split

    float acc[2][4][4];

    for (int c = 0; c < NCH; c++) {
        const int kc = c & 3;

        CP_WAIT(0);        // group for chunk c (committed during iter c-1) landed
        __syncthreads();   // publish slot c&1; all prior reads/writes ordered

        // lag-1 score write: relation (c-1)/4 finished its epilogue in iter c-1
        if (c >= 1 && (c & 3) == 0 && tid < TILE_M)
            sh_sc[((c - 1) >> 2) * TILE_M + tid] = sh_prt[tid] + sh_prt[TILE_M + tid];

        if (kc == 0) {
            #pragma unroll
            for (int mt = 0; mt < 2; mt++)
                #pragma unroll
                for (int nt = 0; nt < 4; nt++)
                    #pragma unroll
                    for (int q = 0; q < 4; q++) acc[mt][nt][q] = 0.f;
        }

        const unsigned* hh = (const unsigned*)(sh_h + (c & 1) * H_SLOT);
        const unsigned* ww = (const unsigned*)(sh_w + (c & 1) * W_SLOT);

        // next-chunk staging bases (hoisted out of the piece loop)
        const bool do_stage = (c + 1 < NCH);
        const float* hsn = nullptr; const float* wsn = nullptr;
        uint32_t hdn = 0, wdn = 0;
        if (do_stage) {
            int cn = c + 1;
            hsn = h + (size_t)(cn >> 2) * NND + (cn & 3) * 32;
            wsn = w1 + (size_t)(cn >> 2) * (DD * AA) + (cn & 3) * (32 * AA);
            hdn = hdst0 + (uint32_t)((cn & 1) * H_SLOT * 4);
            wdn = wdst0 + (uint32_t)((cn & 1) * W_SLOT * 4);
        }

        #pragma unroll
        for (int kt = 0; kt < 4; kt++) {
            // de-burst staging of chunk c+1
            if (do_stage) {
                if (kt < 2) {
                    cp_async16_s(hdn + (2 * kt) * (32 * HCH * 4), hsn + h_off(2 * kt));
                    cp_async16_s(hdn + (2 * kt + 1) * (32 * HCH * 4), hsn + h_off(2 * kt + 1));
                } else if (kt == 2) {
                    cp_async16_s(wdn, wsn + woff0);
                    cp_async16_s(wdn + 16 * WCH * 4, wsn + woff0 + 16 * AA);
                    CP_COMMIT();
                }
            }
            unsigned a[2][4];
            #pragma unroll
            for (int mt = 0; mt < 2; mt++) {
                int row = m0 + mt * 16 + g;
                int col = kt * 8 + tg;
                a[mt][0] = hh[row * HCH + col];
                a[mt][1] = hh[(row + 8) * HCH + col];
                a[mt][2] = hh[row * HCH + col + 4];
                a[mt][3] = hh[(row + 8) * HCH + col + 4];
            }
            #pragma unroll
            for (int nt = 0; nt < 4; nt++) {
                int nb = nh * 32 + nt * 8;
                unsigned b0 = ww[(kt * 8 + tg) * WCH + nb + g];
                unsigned b1 = ww[(kt * 8 + tg + 4) * WCH + nb + g];
                mma_tf32_16n8k8(acc[0][nt], a[0], b0, b1);
                mma_tf32_16n8k8(acc[1][nt], a[1], b0, b1);
            }
        }

        if (kc == 3) {
            const int r = c >> 2;
            float slo[2] = {0.f, 0.f}, shi[2] = {0.f, 0.f};
            #pragma unroll
            for (int mt = 0; mt < 2; mt++)
                #pragma unroll
                for (int nt = 0; nt < 4; nt++) {
                    int cb = nh * 32 + nt * 8 + 2 * tg;
                    float wa = sh_w2[r * AA + cb], wb2 = sh_w2[r * AA + cb + 1];
                    slo[mt] += fast_sigmoid(acc[mt][nt][0]) * wa + fast_sigmoid(acc[mt][nt][1]) * wb2;
                    shi[mt] += fast_sigmoid(acc[mt][nt][2]) * wa + fast_sigmoid(acc[mt][nt][3]) * wb2;
                }
            #pragma unroll
            for (int o = 1; o < 4; o <<= 1) {
                slo[0] += __shfl_xor_sync(0xffffffffu, slo[0], o);
                slo[1] += __shfl_xor_sync(0xffffffffu, slo[1], o);
                shi[0] += __shfl_xor_sync(0xffffffffu, shi[0], o);
                shi[1] += __shfl_xor_sync(0xffffffffu, shi[1], o);
            }
            if (tg == 0) {
                #pragma unroll
                for (int mt = 0; mt < 2; mt++) {
                    sh_prt[nh * TILE_M + m0 + mt * 16 + g]     = slo[mt];
                    sh_prt[nh * TILE_M + m0 + mt * 16 + g + 8] = shi[mt];
                }
            }
        }
    }
    __syncthreads();   // prt for r=7 complete; ring slots final

    // final score (r=7) + softmax over relations
    if (tid < TILE_M) {
        float sv[RR];
        sv[7] = sh_prt[tid] + sh_prt[TILE_M + tid];
        float m = sv[7];
        #pragma unroll
        for (int r = 0; r < 7; r++) { sv[r] = sh_sc[r * TILE_M + tid]; m = fmaxf(m, sv[r]); }
        float sum = 0.f;
        #pragma unroll
        for (int r = 0; r < RR; r++) { sv[r] = fast_exp(sv[r] - m); sum += sv[r]; }
        float inv = 1.f / sum;
        #pragma unroll
        for (int r = 0; r < RR; r++) sh_sc[r * TILE_M + tid] = sv[r] * inv;
    }
    __syncthreads();

    // phase 3: weighted sum. r=7 cols 64..127 from the smem ring
    // (slot0 = chunk30 = k[64:96), slot1 = chunk31 = k[96:128)); rest via .cs.
    const float4* hp = (const float4*)h;
    float4* op = (float4*)out;
    #pragma unroll 4
    for (int i = 0; i < 16; i++) {
        int idx = tid + i * 256;
        int nrow = idx >> 5, c4 = idx & 31;
        long node = node0 + nrow;
        if (node >= NN) continue;

        float a[RR];
        #pragma unroll
        for (int r = 0; r < RR; r++) a[r] = sh_sc[r * TILE_M + nrow];

        float4 acc4;
        {
            float4 v;
            if (c4 < 16) {
                v = ldcs4(&hp[((size_t)7 * NN + node) * 32 + c4]);
            } else {
                const float* sp = sh_h + ((c4 >> 3) & 1) * H_SLOT
                                + nrow * HCH + (c4 & 7) * 4;
                v = *(const float4*)sp;
            }
            acc4.x = a[7] * v.x; acc4.y = a[7] * v.y;
            acc4.z = a[7] * v.z; acc4.w = a[7] * v.w;
        }
        #pragma unroll
        for (int r = 6; r >= 0; r--) {
            float4 v = ldcs4(&hp[((size_t)r * NN + node) * 32 + c4]);
            acc4.x += a[r] * v.x; acc4.y += a[r] * v.y;
            acc4.z += a[r] * v.z; acc4.w += a[r] * v.w;
        }
        stcs4(&op[(size_t)node * 32 + c4], acc4);
    }
}

extern "C" void kernel_launch(void* const* d_in, const int* in_sizes, int n_in,
                              void* d_out, int out_size) {
    const float* h  = (const float*)d_in[0];
    const float* w1 = (const float*)d_in[1];
    const float* w2 = (const float*)d_in[2];
    float* out = (float*)d_out;

    const int smem_bytes =
        (2 * H_SLOT + 2 * W_SLOT + RR * AA + RR * TILE_M + 2 * TILE_M) * 4;  // ~61 KB
    cudaFuncSetAttribute(fused_kernel,
                         cudaFuncAttributeMaxDynamicSharedMemorySize, smem_bytes);

    dim3 grid((NN + TILE_M - 1) / TILE_M);
    fused_kernel<<<grid, 256, smem_bytes>>>(h, w1, w2, out);
}